// round 14
// baseline (speedup 1.0000x reference)
#include <cuda_runtime.h>
#include <cuda_fp16.h>
#include <math.h>

#define N_  4
#define L_  2048
#define D_  512
#define H_  8
#define DK_ 64
#define M_  (N_ * L_)

// Scratch (device globals: no allocation allowed in kernel_launch)
__device__ __half g_xqh[(size_t)M_ * D_];
__device__ __half g_xkh[(size_t)M_ * D_];
__device__ __half g_xvh[(size_t)M_ * D_];
__device__ __half g_wqh[(size_t)D_ * D_];
__device__ __half g_wkh[(size_t)D_ * D_];
__device__ __half g_wvh[(size_t)D_ * D_];
__device__ __half g_woh[(size_t)D_ * D_];
__device__ __half g_Qh[(size_t)M_ * D_];
__device__ __half g_Kh[(size_t)M_ * D_];
__device__ __half g_Vh[(size_t)M_ * D_];
__device__ __half g_Oh[(size_t)M_ * D_];
__device__ int    g_len[N_];

#define HONES 0x3C003C00u   // half2(1.0, 1.0)

// ---------------------------------------------------------------------------
__device__ __forceinline__ void mma16(float c[4], const unsigned a[4],
                                      unsigned b0, unsigned b1) {
    asm volatile(
        "mma.sync.aligned.m16n8k16.row.col.f32.f16.f16.f32 "
        "{%0,%1,%2,%3}, {%4,%5,%6,%7}, {%8,%9}, {%0,%1,%2,%3};\n"
        : "+f"(c[0]), "+f"(c[1]), "+f"(c[2]), "+f"(c[3])
        : "r"(a[0]), "r"(a[1]), "r"(a[2]), "r"(a[3]), "r"(b0), "r"(b1));
}

__device__ __forceinline__ unsigned smaddr(const void* p) {
    return (unsigned)__cvta_generic_to_shared(p);
}
#define LDM_X4(r0, r1, r2, r3, addr) \
    asm volatile("ldmatrix.sync.aligned.m8n8.x4.shared.b16 {%0,%1,%2,%3}, [%4];" \
        : "=r"(r0), "=r"(r1), "=r"(r2), "=r"(r3) : "r"(addr))
#define LDM_X4T(r0, r1, r2, r3, addr) \
    asm volatile("ldmatrix.sync.aligned.m8n8.x4.trans.shared.b16 {%0,%1,%2,%3}, [%4];" \
        : "=r"(r0), "=r"(r1), "=r"(r2), "=r"(r3) : "r"(addr))
#define CP16(sm, gm) asm volatile("cp.async.cg.shared.global [%0], [%1], 16;\n" :: "r"(sm), "l"(gm))
#define CP_COMMIT()  asm volatile("cp.async.commit_group;\n")
#define CP_WAIT(n)   asm volatile("cp.async.wait_group %0;\n" :: "n"(n))

__device__ __forceinline__ unsigned h2bits(float lo, float hi) {
    __half2 h = __floats2half2_rn(lo, hi);
    return *(unsigned*)&h;
}

// packed half2 2^x
__device__ __forceinline__ unsigned ex2h2(unsigned x) {
    unsigned r;
    asm volatile("ex2.approx.f16x2 %0, %1;" : "=r"(r) : "r"(x));
    return r;
}

// ---------------------------------------------------------------------------
// prep: one launch does all float->half conversions AND the len reduction.
// blockIdx.y: 0..2 -> x_q/x_k/x_v (X4 float4s), 3..6 -> weights (W4 float4s),
//             7 -> len (4 blocks, one per batch).
// ---------------------------------------------------------------------------
#define X4_ (M_ * D_ / 4)
#define W4_ (D_ * D_ / 4)

__global__ void prep_kernel(const float4* __restrict__ xq,
                            const float4* __restrict__ xk,
                            const float4* __restrict__ xv,
                            const float4* __restrict__ Wq,
                            const float4* __restrict__ Wk,
                            const float4* __restrict__ Wv,
                            const float4* __restrict__ Wo,
                            const int* __restrict__ pm) {
    int y = blockIdx.y;
    if (y < 3) {
        const float4* s = (y == 0) ? xq : (y == 1) ? xk : xv;
        uint2* d = (y == 0) ? (uint2*)g_xqh : (y == 1) ? (uint2*)g_xkh : (uint2*)g_xvh;
        int i = blockIdx.x * 512 + threadIdx.x;
        float4 v0 = s[i], v1 = s[i + 256];
        d[i]       = make_uint2(h2bits(v0.x, v0.y), h2bits(v0.z, v0.w));
        d[i + 256] = make_uint2(h2bits(v1.x, v1.y), h2bits(v1.z, v1.w));
    } else if (y < 7) {
        if (blockIdx.x >= W4_ / 512) return;
        const float4* s = (y == 3) ? Wq : (y == 4) ? Wk : (y == 5) ? Wv : Wo;
        uint2* d = (y == 3) ? (uint2*)g_wqh : (y == 4) ? (uint2*)g_wkh
                 : (y == 5) ? (uint2*)g_wvh : (uint2*)g_woh;
        int i = blockIdx.x * 512 + threadIdx.x;
        float4 v0 = s[i], v1 = s[i + 256];
        d[i]       = make_uint2(h2bits(v0.x, v0.y), h2bits(v0.z, v0.w));
        d[i + 256] = make_uint2(h2bits(v1.x, v1.y), h2bits(v1.z, v1.w));
    } else {
        if (blockIdx.x >= N_) return;
        __shared__ int red[8];
        int n = blockIdx.x;
        int best = 0;
        for (int j = threadIdx.x; j < L_; j += 256)
            if (pm[(size_t)n * L_ + j] != 0) best = max(best, j + 1);
        #pragma unroll
        for (int off = 16; off; off >>= 1)
            best = max(best, __shfl_xor_sync(0xffffffffu, best, off));
        if ((threadIdx.x & 31) == 0) red[threadIdx.x >> 5] = best;
        __syncthreads();
        if (threadIdx.x == 0) {
            int b = red[0];
            #pragma unroll
            for (int w = 1; w < 8; w++) b = max(b, red[w]);
            g_len[n] = b;
        }
    }
}

// ---------------------------------------------------------------------------
// GEMM body (R10): 128x128 tile, 256 threads, 8 warps (64x32 warp tile),
// fp16 mma, cp.async 3-stage pipelined chunks (K=64).
// ---------------------------------------------------------------------------
#define GST 72
#define GNB (128 * GST)
#define GEMM_SMEM (3 * 2 * GNB * (int)sizeof(__half))

__device__ __forceinline__ void gemm_stage(__half* As, __half* Ws,
                                           const __half* __restrict__ A,
                                           const __half* __restrict__ W,
                                           int row0, int col0, int k0, int tid) {
    #pragma unroll
    for (int i = 0; i < 4; i++) {
        int idx = tid + i * 256;
        int r = idx >> 3, u = idx & 7;
        CP16(smaddr(&As[r * GST + u * 8]), A + (size_t)(row0 + r) * D_ + k0 + u * 8);
        CP16(smaddr(&Ws[r * GST + u * 8]), W + (size_t)(col0 + r) * D_ + k0 + u * 8);
    }
}

__device__ __forceinline__ void gemm_body(
    const __half* __restrict__ A, const __half* __restrict__ W,
    const float* __restrict__ bias, void* __restrict__ Cout, float scale,
    int half_out)
{
    extern __shared__ __half gsm[];
    __half* As = gsm;            // [3][GNB]
    __half* Ws = gsm + 3 * GNB;  // [3][GNB]

    int tid  = threadIdx.x;
    int lane = tid & 31, warp = tid >> 5;
    int g = lane >> 2, t = lane & 3;
    int wm = warp & 1, wn = warp >> 1;
    int row0 = blockIdx.x * 128;
    int col0 = blockIdx.y * 128;

    int arow = ((lane >> 3) & 1) * 8 + (lane & 7);
    int acol = (lane >> 4) * 8;
    int brow = (lane >> 4) * 8 + (lane & 7);
    int bcol = ((lane >> 3) & 1) * 8;

    float c[4][4][4];
    #pragma unroll
    for (int mf = 0; mf < 4; mf++)
        #pragma unroll
        for (int nf = 0; nf < 4; nf++)
            #pragma unroll
            for (int i = 0; i < 4; i++) c[mf][nf][i] = 0.f;

    gemm_stage(As,       Ws,       A, W, row0, col0, 0,  tid); CP_COMMIT();
    gemm_stage(As + GNB, Ws + GNB, A, W, row0, col0, 64, tid); CP_COMMIT();

    #pragma unroll 1
    for (int ch = 0; ch < 8; ch++) {
        int bi = ch % 3;
        if (ch < 7) { CP_WAIT(1); } else { CP_WAIT(0); }
        __syncthreads();
        if (ch + 2 < 8) {
            int nb = (ch + 2) % 3;
            gemm_stage(As + nb * GNB, Ws + nb * GNB, A, W, row0, col0,
                       (ch + 2) * 64, tid);
            CP_COMMIT();
        }

        const __half* Ab = As + bi * GNB;
        const __half* Wb = Ws + bi * GNB;

        #pragma unroll
        for (int kk = 0; kk < 4; kk++) {
            unsigned a[4][4], b[4][2];
            #pragma unroll
            for (int mf = 0; mf < 4; mf++) {
                unsigned addr = smaddr(&Ab[(wm * 64 + mf * 16 + arow) * GST + kk * 16 + acol]);
                LDM_X4(a[mf][0], a[mf][1], a[mf][2], a[mf][3], addr);
            }
            #pragma unroll
            for (int np = 0; np < 2; np++) {
                unsigned addr = smaddr(&Wb[(wn * 32 + np * 16 + brow) * GST + kk * 16 + bcol]);
                LDM_X4(b[2 * np][0], b[2 * np][1], b[2 * np + 1][0], b[2 * np + 1][1], addr);
            }
            #pragma unroll
            for (int mf = 0; mf < 4; mf++)
                #pragma unroll
                for (int nf = 0; nf < 4; nf++)
                    mma16(c[mf][nf], a[mf], b[nf][0], b[nf][1]);
        }
    }

    // Epilogue
    #pragma unroll
    for (int mf = 0; mf < 4; mf++) {
        int r0 = row0 + wm * 64 + mf * 16 + g;
        #pragma unroll
        for (int nf = 0; nf < 4; nf++) {
            int cc = col0 + wn * 32 + nf * 8 + 2 * t;
            float b0 = bias[cc], b1 = bias[cc + 1];
            float v00 = (c[mf][nf][0] + b0) * scale;
            float v01 = (c[mf][nf][1] + b1) * scale;
            float v10 = (c[mf][nf][2] + b0) * scale;
            float v11 = (c[mf][nf][3] + b1) * scale;
            if (half_out) {
                __half* C = (__half*)Cout;
                *(unsigned*)(C + (size_t)r0 * D_ + cc)       = h2bits(v00, v01);
                *(unsigned*)(C + (size_t)(r0 + 8) * D_ + cc) = h2bits(v10, v11);
            } else {
                float* C = (float*)Cout;
                *(float2*)(C + (size_t)r0 * D_ + cc)       = make_float2(v00, v01);
                *(float2*)(C + (size_t)(r0 + 8) * D_ + cc) = make_float2(v10, v11);
            }
        }
    }
}

// Fused Q/K/V projection. Q scale folds 1/sqrt(dk) and log2(e) -> exp2 domain.
__global__ __launch_bounds__(256, 2) void gemm_qkv(
    const __half* __restrict__ xq, const __half* __restrict__ xk,
    const __half* __restrict__ xv,
    const __half* __restrict__ wq, const __half* __restrict__ wk,
    const __half* __restrict__ wv,
    const float* __restrict__ bq, const float* __restrict__ bk,
    const float* __restrict__ bv,
    __half* __restrict__ Q, __half* __restrict__ K, __half* __restrict__ V)
{
    int z = blockIdx.z;
    const __half* A = (z == 0) ? xq : (z == 1) ? xk : xv;
    const __half* W = (z == 0) ? wq : (z == 1) ? wk : wv;
    const float* bias = (z == 0) ? bq : (z == 1) ? bk : bv;
    __half* C = (z == 0) ? Q : (z == 1) ? K : V;
    float scale = (z == 0) ? (0.125f * 1.4426950408889634f) : 1.0f;
    gemm_body(A, W, bias, C, scale, 1);
}

__global__ __launch_bounds__(256, 2) void gemm_o(
    const __half* __restrict__ A, const __half* __restrict__ W,
    const float* __restrict__ bias, float* __restrict__ C)
{
    gemm_body(A, W, bias, C, 1.0f, 0);
}

// ---------------------------------------------------------------------------
// Flash attention, fp16 mma. Block = (256 q-rows, head, batch), 8 warps,
// 32 q-rows per warp. KV tiles shared across all 256 rows (half the staging
// traffic vs 128-row blocks). log2-domain, ex2.f16x2, ones-column row sums.
// Heavy (high-q0) blocks first.
// ---------------------------------------------------------------------------
#define AST 72
#define ATTN_SMEM (4 * 64 * AST * (int)sizeof(__half))

__global__ __launch_bounds__(256) void attn_h(int dummy) {
    extern __shared__ __half asm_[];
    __half* Ks = asm_;                        // [2][64*AST]
    __half* Vs = asm_ + 2 * 64 * AST;         // [2][64*AST]

    int tid  = threadIdx.x;
    int lane = tid & 31, warp = tid >> 5;
    int g = lane >> 2, t = lane & 3;
    int q0 = ((int)gridDim.x - 1 - (int)blockIdx.x) * 256;
    int h  = blockIdx.y;
    int n  = blockIdx.z;

    int row_w = q0 + warp * 32;    // 32 rows per warp, 8 warps = 256 rows

    const __half* Qg = g_Qh + (size_t)n * L_ * D_ + (size_t)row_w * D_ + h * DK_;
    const __half* Kg = g_Kh + (size_t)n * L_ * D_ + h * DK_;
    const __half* Vg = g_Vh + (size_t)n * L_ * D_ + h * DK_;

    int brow = (lane >> 4) * 8 + (lane & 7);
    int bcol = ((lane >> 3) & 1) * 8;
    int vrow = ((lane >> 3) & 1) * 8 + (lane & 7);
    int vcol = (lane >> 4) * 8;

    // Q fragments: 2 row-sets of 16 rows each
    unsigned qa[2][4][4];
    #pragma unroll
    for (int s = 0; s < 2; s++)
        #pragma unroll
        for (int kk = 0; kk < 4; kk++) {
            qa[s][kk][0] = *(const unsigned*)&Qg[(size_t)(s * 16 + g) * D_     + kk * 16 + 2 * t];
            qa[s][kk][1] = *(const unsigned*)&Qg[(size_t)(s * 16 + g + 8) * D_ + kk * 16 + 2 * t];
            qa[s][kk][2] = *(const unsigned*)&Qg[(size_t)(s * 16 + g) * D_     + kk * 16 + 2 * t + 8];
            qa[s][kk][3] = *(const unsigned*)&Qg[(size_t)(s * 16 + g + 8) * D_ + kk * 16 + 2 * t + 8];
        }

    float oc[2][8][4];
    #pragma unroll
    for (int s = 0; s < 2; s++)
        #pragma unroll
        for (int nf = 0; nf < 8; nf++)
            #pragma unroll
            for (int i = 0; i < 4; i++) oc[s][nf][i] = 0.f;
    float ol[2][4];
    #pragma unroll
    for (int s = 0; s < 2; s++)
        #pragma unroll
        for (int i = 0; i < 4; i++) ol[s][i] = 0.f;

    float m[2][2];
    m[0][0] = m[0][1] = m[1][0] = m[1][1] = -1e30f;
    int rmax_w = row_w + 31;

    int len   = g_len[n];
    int jend  = min(q0 + 256, len);
    int tiles = (jend + 63) >> 6;

    // prologue: tile 0 (K, V) — 256 threads stage 64x64-half K and V
    {
        #pragma unroll
        for (int i = 0; i < 2; i++) {
            int idx = tid + i * 256;      // 0..511
            int r = idx >> 3, u = idx & 7;
            CP16(smaddr(&Ks[r * AST + u * 8]), Kg + (size_t)r * D_ + u * 8);
            CP16(smaddr(&Vs[r * AST + u * 8]), Vg + (size_t)r * D_ + u * 8);
        }
        CP_COMMIT();
    }

    #pragma unroll 1
    for (int it = 0; it < tiles; it++) {
        int cur = it & 1;
        int j0  = it * 64;
        if (it + 1 < tiles) {
            int jn = j0 + 64;
            __half* Kd = Ks + (cur ^ 1) * 64 * AST;
            __half* Vd = Vs + (cur ^ 1) * 64 * AST;
            #pragma unroll
            for (int i = 0; i < 2; i++) {
                int idx = tid + i * 256;
                int r = idx >> 3, u = idx & 7;
                CP16(smaddr(&Kd[r * AST + u * 8]), Kg + (size_t)(jn + r) * D_ + u * 8);
                CP16(smaddr(&Vd[r * AST + u * 8]), Vg + (size_t)(jn + r) * D_ + u * 8);
            }
            CP_COMMIT();
            CP_WAIT(1);
        } else {
            CP_WAIT(0);
        }
        __syncthreads();

        if (j0 <= rmax_w) {
            const __half* Kb = Ks + cur * 64 * AST;
            const __half* Vb = Vs + cur * 64 * AST;

            // S = Q K^T (log2 domain), both row-sets share K fragments
            float sc[2][8][4];
            #pragma unroll
            for (int s = 0; s < 2; s++)
                #pragma unroll
                for (int nf = 0; nf < 8; nf++)
                    #pragma unroll
                    for (int i = 0; i < 4; i++) sc[s][nf][i] = 0.f;

            #pragma unroll
            for (int kk = 0; kk < 4; kk++) {
                unsigned b[8][2];
                #pragma unroll
                for (int np = 0; np < 4; np++) {
                    unsigned addr = smaddr(&Kb[(np * 16 + brow) * AST + kk * 16 + bcol]);
                    LDM_X4(b[2 * np][0], b[2 * np][1], b[2 * np + 1][0], b[2 * np + 1][1], addr);
                }
                #pragma unroll
                for (int nf = 0; nf < 8; nf++) {
                    mma16(sc[0][nf], qa[0][kk], b[nf][0], b[nf][1]);
                    mma16(sc[1][nf], qa[1][kk], b[nf][0], b[nf][1]);
                }
            }

            // Masking only on diagonal / len-boundary tiles
            bool need_mask = (j0 + 63 > row_w) || (j0 + 64 > len);
            if (need_mask) {
                #pragma unroll
                for (int s = 0; s < 2; s++) {
                    int r0 = row_w + s * 16 + g;
                    int r1 = r0 + 8;
                    #pragma unroll
                    for (int nf = 0; nf < 8; nf++) {
                        int c0i = j0 + nf * 8 + 2 * t, c1i = c0i + 1;
                        if (c0i > r0 || c0i >= len) sc[s][nf][0] = -1e30f;
                        if (c1i > r0 || c1i >= len) sc[s][nf][1] = -1e30f;
                        if (c0i > r1 || c0i >= len) sc[s][nf][2] = -1e30f;
                        if (c1i > r1 || c1i >= len) sc[s][nf][3] = -1e30f;
                    }
                }
            }

            // Row max + rescale per set
            #pragma unroll
            for (int s = 0; s < 2; s++) {
                float rm0 = -1e30f, rm1 = -1e30f;
                #pragma unroll
                for (int nf = 0; nf < 8; nf++) {
                    rm0 = fmaxf(rm0, fmaxf(sc[s][nf][0], sc[s][nf][1]));
                    rm1 = fmaxf(rm1, fmaxf(sc[s][nf][2], sc[s][nf][3]));
                }
                rm0 = fmaxf(rm0, __shfl_xor_sync(0xffffffffu, rm0, 1));
                rm0 = fmaxf(rm0, __shfl_xor_sync(0xffffffffu, rm0, 2));
                rm1 = fmaxf(rm1, __shfl_xor_sync(0xffffffffu, rm1, 1));
                rm1 = fmaxf(rm1, __shfl_xor_sync(0xffffffffu, rm1, 2));

                float mn0 = fmaxf(m[s][0], rm0), mn1 = fmaxf(m[s][1], rm1);
                float al0 = exp2f(m[s][0] - mn0), al1 = exp2f(m[s][1] - mn1);
                m[s][0] = mn0; m[s][1] = mn1;

                #pragma unroll
                for (int nf = 0; nf < 8; nf++) {
                    oc[s][nf][0] *= al0; oc[s][nf][1] *= al0;
                    oc[s][nf][2] *= al1; oc[s][nf][3] *= al1;
                }
                ol[s][0] *= al0; ol[s][1] *= al0;
                ol[s][2] *= al1; ol[s][3] *= al1;
            }

            // P = exp2(S - m) fp16; V fragments shared by both sets
            #pragma unroll
            for (int kk = 0; kk < 4; kk++) {
                unsigned pa[2][4];
                #pragma unroll
                for (int s = 0; s < 2; s++) {
                    pa[s][0] = ex2h2(h2bits(sc[s][2 * kk][0] - m[s][0],     sc[s][2 * kk][1] - m[s][0]));
                    pa[s][1] = ex2h2(h2bits(sc[s][2 * kk][2] - m[s][1],     sc[s][2 * kk][3] - m[s][1]));
                    pa[s][2] = ex2h2(h2bits(sc[s][2 * kk + 1][0] - m[s][0], sc[s][2 * kk + 1][1] - m[s][0]));
                    pa[s][3] = ex2h2(h2bits(sc[s][2 * kk + 1][2] - m[s][1], sc[s][2 * kk + 1][3] - m[s][1]));
                }
                #pragma unroll
                for (int np = 0; np < 4; np++) {
                    unsigned v0, v1, v2, v3;
                    unsigned addr = smaddr(&Vb[(kk * 16 + vrow) * AST + np * 16 + vcol]);
                    LDM_X4T(v0, v1, v2, v3, addr);
                    mma16(oc[0][2 * np],     pa[0], v0, v1);
                    mma16(oc[0][2 * np + 1], pa[0], v2, v3);
                    mma16(oc[1][2 * np],     pa[1], v0, v1);
                    mma16(oc[1][2 * np + 1], pa[1], v2, v3);
                }
                mma16(ol[0], pa[0], HONES, HONES);
                mma16(ol[1], pa[1], HONES, HONES);
            }
        }
        __syncthreads();
    }

    // Epilogue: normalize by MMA-accumulated row sums, write O (half)
    #pragma unroll
    for (int s = 0; s < 2; s++) {
        float inv0 = 1.0f / ol[s][0], inv1 = 1.0f / ol[s][2];
        __half* Og = g_Oh + ((size_t)(n * L_ + row_w + s * 16)) * D_ + h * DK_;
        #pragma unroll
        for (int nf = 0; nf < 8; nf++) {
            int cb = nf * 8 + 2 * t;
            *(unsigned*)(Og + (size_t)g * D_ + cb) =
                h2bits(oc[s][nf][0] * inv0, oc[s][nf][1] * inv0);
            *(unsigned*)(Og + (size_t)(g + 8) * D_ + cb) =
                h2bits(oc[s][nf][2] * inv1, oc[s][nf][3] * inv1);
        }
    }
}

// ---------------------------------------------------------------------------
extern "C" void kernel_launch(void* const* d_in, const int* in_sizes, int n_in,
                              void* d_out, int out_size)
{
    const float* x_q = (const float*)d_in[0];
    const float* x_k = (const float*)d_in[1];
    const float* x_v = (const float*)d_in[2];
    const int*   pm  = (const int*)  d_in[3];
    // d_in[4] = attention_mask (causal) — handled analytically
    const float* Wq = (const float*)d_in[5];
    const float* bq = (const float*)d_in[6];
    const float* Wk = (const float*)d_in[7];
    const float* bk = (const float*)d_in[8];
    const float* Wv = (const float*)d_in[9];
    const float* bv = (const float*)d_in[10];
    const float* Wo = (const float*)d_in[11];
    const float* bo = (const float*)d_in[12];
    float* out = (float*)d_out;

    __half *xqh, *xkh, *xvh, *wqh, *wkh, *wvh, *woh, *Qh, *Kh, *Vh, *Oh;
    cudaGetSymbolAddress((void**)&xqh, g_xqh);
    cudaGetSymbolAddress((void**)&xkh, g_xkh);
    cudaGetSymbolAddress((void**)&xvh, g_xvh);
    cudaGetSymbolAddress((void**)&wqh, g_wqh);
    cudaGetSymbolAddress((void**)&wkh, g_wkh);
    cudaGetSymbolAddress((void**)&wvh, g_wvh);
    cudaGetSymbolAddress((void**)&woh, g_woh);
    cudaGetSymbolAddress((void**)&Qh,  g_Qh);
    cudaGetSymbolAddress((void**)&Kh,  g_Kh);
    cudaGetSymbolAddress((void**)&Vh,  g_Vh);
    cudaGetSymbolAddress((void**)&Oh,  g_Oh);

    cudaFuncSetAttribute(gemm_qkv, cudaFuncAttributeMaxDynamicSharedMemorySize,
                         GEMM_SMEM);
    cudaFuncSetAttribute(gemm_o, cudaFuncAttributeMaxDynamicSharedMemorySize,
                         GEMM_SMEM);
    cudaFuncSetAttribute(attn_h, cudaFuncAttributeMaxDynamicSharedMemorySize,
                         ATTN_SMEM);

    // One prep launch: x/W conversions + len reduction
    prep_kernel<<<dim3(X4_ / 512, 8), 256>>>(
        (const float4*)x_q, (const float4*)x_k, (const float4*)x_v,
        (const float4*)Wq, (const float4*)Wk, (const float4*)Wv,
        (const float4*)Wo, pm);

    gemm_qkv<<<dim3(M_ / 128, D_ / 128, 3), 256, GEMM_SMEM>>>(
        xqh, xkh, xvh, wqh, wkh, wvh, bq, bk, bv, Qh, Kh, Vh);

    attn_h<<<dim3(L_ / 256, H_, N_), 256, ATTN_SMEM>>>(0);

    gemm_o<<<dim3(M_ / 128, D_ / 128), 256, GEMM_SMEM>>>(Oh, woh, bo, out);
}

// round 15
// speedup vs baseline: 1.0930x; 1.0930x over previous
#include <cuda_runtime.h>
#include <cuda_fp16.h>
#include <math.h>

#define N_  4
#define L_  2048
#define D_  512
#define H_  8
#define DK_ 64
#define M_  (N_ * L_)

// Scratch (device globals: no allocation allowed in kernel_launch)
__device__ __half g_xqh[(size_t)M_ * D_];
__device__ __half g_xkh[(size_t)M_ * D_];
__device__ __half g_xvh[(size_t)M_ * D_];
__device__ __half g_wqh[(size_t)D_ * D_];
__device__ __half g_wkh[(size_t)D_ * D_];
__device__ __half g_wvh[(size_t)D_ * D_];
__device__ __half g_woh[(size_t)D_ * D_];
__device__ __half g_Qh[(size_t)M_ * D_];
__device__ __half g_Kh[(size_t)M_ * D_];
__device__ __half g_Vh[(size_t)M_ * D_];
__device__ __half g_Oh[(size_t)M_ * D_];
__device__ int    g_len[N_];

#define HONES 0x3C003C00u   // half2(1.0, 1.0)

// ---------------------------------------------------------------------------
__device__ __forceinline__ void mma16(float c[4], const unsigned a[4],
                                      unsigned b0, unsigned b1) {
    asm volatile(
        "mma.sync.aligned.m16n8k16.row.col.f32.f16.f16.f32 "
        "{%0,%1,%2,%3}, {%4,%5,%6,%7}, {%8,%9}, {%0,%1,%2,%3};\n"
        : "+f"(c[0]), "+f"(c[1]), "+f"(c[2]), "+f"(c[3])
        : "r"(a[0]), "r"(a[1]), "r"(a[2]), "r"(a[3]), "r"(b0), "r"(b1));
}

__device__ __forceinline__ unsigned smaddr(const void* p) {
    return (unsigned)__cvta_generic_to_shared(p);
}
#define LDM_X4(r0, r1, r2, r3, addr) \
    asm volatile("ldmatrix.sync.aligned.m8n8.x4.shared.b16 {%0,%1,%2,%3}, [%4];" \
        : "=r"(r0), "=r"(r1), "=r"(r2), "=r"(r3) : "r"(addr))
#define LDM_X4T(r0, r1, r2, r3, addr) \
    asm volatile("ldmatrix.sync.aligned.m8n8.x4.trans.shared.b16 {%0,%1,%2,%3}, [%4];" \
        : "=r"(r0), "=r"(r1), "=r"(r2), "=r"(r3) : "r"(addr))
#define CP16(sm, gm) asm volatile("cp.async.cg.shared.global [%0], [%1], 16;\n" :: "r"(sm), "l"(gm))
#define CP_COMMIT()  asm volatile("cp.async.commit_group;\n")
#define CP_WAIT(n)   asm volatile("cp.async.wait_group %0;\n" :: "n"(n))

__device__ __forceinline__ unsigned h2bits(float lo, float hi) {
    __half2 h = __floats2half2_rn(lo, hi);
    return *(unsigned*)&h;
}

// packed half2 2^x
__device__ __forceinline__ unsigned ex2h2(unsigned x) {
    unsigned r;
    asm volatile("ex2.approx.f16x2 %0, %1;" : "=r"(r) : "r"(x));
    return r;
}

// ---------------------------------------------------------------------------
// prep: one launch does all float->half conversions AND the len reduction.
// blockIdx.y: 0..2 -> x_q/x_k/x_v, 3..6 -> weights, 7 -> len.
// ---------------------------------------------------------------------------
#define X4_ (M_ * D_ / 4)
#define W4_ (D_ * D_ / 4)

__global__ void prep_kernel(const float4* __restrict__ xq,
                            const float4* __restrict__ xk,
                            const float4* __restrict__ xv,
                            const float4* __restrict__ Wq,
                            const float4* __restrict__ Wk,
                            const float4* __restrict__ Wv,
                            const float4* __restrict__ Wo,
                            const int* __restrict__ pm) {
    int y = blockIdx.y;
    if (y < 3) {
        const float4* s = (y == 0) ? xq : (y == 1) ? xk : xv;
        uint2* d = (y == 0) ? (uint2*)g_xqh : (y == 1) ? (uint2*)g_xkh : (uint2*)g_xvh;
        int i = blockIdx.x * 512 + threadIdx.x;
        float4 v0 = s[i], v1 = s[i + 256];
        d[i]       = make_uint2(h2bits(v0.x, v0.y), h2bits(v0.z, v0.w));
        d[i + 256] = make_uint2(h2bits(v1.x, v1.y), h2bits(v1.z, v1.w));
    } else if (y < 7) {
        if (blockIdx.x >= W4_ / 512) return;
        const float4* s = (y == 3) ? Wq : (y == 4) ? Wk : (y == 5) ? Wv : Wo;
        uint2* d = (y == 3) ? (uint2*)g_wqh : (y == 4) ? (uint2*)g_wkh
                 : (y == 5) ? (uint2*)g_wvh : (uint2*)g_woh;
        int i = blockIdx.x * 512 + threadIdx.x;
        float4 v0 = s[i], v1 = s[i + 256];
        d[i]       = make_uint2(h2bits(v0.x, v0.y), h2bits(v0.z, v0.w));
        d[i + 256] = make_uint2(h2bits(v1.x, v1.y), h2bits(v1.z, v1.w));
    } else {
        if (blockIdx.x >= N_) return;
        __shared__ int red[8];
        int n = blockIdx.x;
        int best = 0;
        for (int j = threadIdx.x; j < L_; j += 256)
            if (pm[(size_t)n * L_ + j] != 0) best = max(best, j + 1);
        #pragma unroll
        for (int off = 16; off; off >>= 1)
            best = max(best, __shfl_xor_sync(0xffffffffu, best, off));
        if ((threadIdx.x & 31) == 0) red[threadIdx.x >> 5] = best;
        __syncthreads();
        if (threadIdx.x == 0) {
            int b = red[0];
            #pragma unroll
            for (int w = 1; w < 8; w++) b = max(b, red[w]);
            g_len[n] = b;
        }
    }
}

// ---------------------------------------------------------------------------
// GEMM body (R10): 128x128 tile, 256 threads, 8 warps (64x32 warp tile),
// fp16 mma, cp.async 3-stage pipelined chunks (K=64).
// ---------------------------------------------------------------------------
#define GST 72
#define GNB (128 * GST)
#define GEMM_SMEM (3 * 2 * GNB * (int)sizeof(__half))

__device__ __forceinline__ void gemm_stage(__half* As, __half* Ws,
                                           const __half* __restrict__ A,
                                           const __half* __restrict__ W,
                                           int row0, int col0, int k0, int tid) {
    #pragma unroll
    for (int i = 0; i < 4; i++) {
        int idx = tid + i * 256;
        int r = idx >> 3, u = idx & 7;
        CP16(smaddr(&As[r * GST + u * 8]), A + (size_t)(row0 + r) * D_ + k0 + u * 8);
        CP16(smaddr(&Ws[r * GST + u * 8]), W + (size_t)(col0 + r) * D_ + k0 + u * 8);
    }
}

__device__ __forceinline__ void gemm_body(
    const __half* __restrict__ A, const __half* __restrict__ W,
    const float* __restrict__ bias, void* __restrict__ Cout, float scale,
    int half_out)
{
    extern __shared__ __half gsm[];
    __half* As = gsm;            // [3][GNB]
    __half* Ws = gsm + 3 * GNB;  // [3][GNB]

    int tid  = threadIdx.x;
    int lane = tid & 31, warp = tid >> 5;
    int g = lane >> 2, t = lane & 3;
    int wm = warp & 1, wn = warp >> 1;
    int row0 = blockIdx.x * 128;
    int col0 = blockIdx.y * 128;

    int arow = ((lane >> 3) & 1) * 8 + (lane & 7);
    int acol = (lane >> 4) * 8;
    int brow = (lane >> 4) * 8 + (lane & 7);
    int bcol = ((lane >> 3) & 1) * 8;

    float c[4][4][4];
    #pragma unroll
    for (int mf = 0; mf < 4; mf++)
        #pragma unroll
        for (int nf = 0; nf < 4; nf++)
            #pragma unroll
            for (int i = 0; i < 4; i++) c[mf][nf][i] = 0.f;

    gemm_stage(As,       Ws,       A, W, row0, col0, 0,  tid); CP_COMMIT();
    gemm_stage(As + GNB, Ws + GNB, A, W, row0, col0, 64, tid); CP_COMMIT();

    #pragma unroll 1
    for (int ch = 0; ch < 8; ch++) {
        int bi = ch % 3;
        if (ch < 7) { CP_WAIT(1); } else { CP_WAIT(0); }
        __syncthreads();
        if (ch + 2 < 8) {
            int nb = (ch + 2) % 3;
            gemm_stage(As + nb * GNB, Ws + nb * GNB, A, W, row0, col0,
                       (ch + 2) * 64, tid);
            CP_COMMIT();
        }

        const __half* Ab = As + bi * GNB;
        const __half* Wb = Ws + bi * GNB;

        #pragma unroll
        for (int kk = 0; kk < 4; kk++) {
            unsigned a[4][4], b[4][2];
            #pragma unroll
            for (int mf = 0; mf < 4; mf++) {
                unsigned addr = smaddr(&Ab[(wm * 64 + mf * 16 + arow) * GST + kk * 16 + acol]);
                LDM_X4(a[mf][0], a[mf][1], a[mf][2], a[mf][3], addr);
            }
            #pragma unroll
            for (int np = 0; np < 2; np++) {
                unsigned addr = smaddr(&Wb[(wn * 32 + np * 16 + brow) * GST + kk * 16 + bcol]);
                LDM_X4(b[2 * np][0], b[2 * np][1], b[2 * np + 1][0], b[2 * np + 1][1], addr);
            }
            #pragma unroll
            for (int mf = 0; mf < 4; mf++)
                #pragma unroll
                for (int nf = 0; nf < 4; nf++)
                    mma16(c[mf][nf], a[mf], b[nf][0], b[nf][1]);
        }
    }

    // Epilogue
    #pragma unroll
    for (int mf = 0; mf < 4; mf++) {
        int r0 = row0 + wm * 64 + mf * 16 + g;
        #pragma unroll
        for (int nf = 0; nf < 4; nf++) {
            int cc = col0 + wn * 32 + nf * 8 + 2 * t;
            float b0 = bias[cc], b1 = bias[cc + 1];
            float v00 = (c[mf][nf][0] + b0) * scale;
            float v01 = (c[mf][nf][1] + b1) * scale;
            float v10 = (c[mf][nf][2] + b0) * scale;
            float v11 = (c[mf][nf][3] + b1) * scale;
            if (half_out) {
                __half* C = (__half*)Cout;
                *(unsigned*)(C + (size_t)r0 * D_ + cc)       = h2bits(v00, v01);
                *(unsigned*)(C + (size_t)(r0 + 8) * D_ + cc) = h2bits(v10, v11);
            } else {
                float* C = (float*)Cout;
                *(float2*)(C + (size_t)r0 * D_ + cc)       = make_float2(v00, v01);
                *(float2*)(C + (size_t)(r0 + 8) * D_ + cc) = make_float2(v10, v11);
            }
        }
    }
}

// Fused Q/K/V projection. Q scale folds 1/sqrt(dk) and log2(e) -> exp2 domain.
__global__ __launch_bounds__(256, 2) void gemm_qkv(
    const __half* __restrict__ xq, const __half* __restrict__ xk,
    const __half* __restrict__ xv,
    const __half* __restrict__ wq, const __half* __restrict__ wk,
    const __half* __restrict__ wv,
    const float* __restrict__ bq, const float* __restrict__ bk,
    const float* __restrict__ bv,
    __half* __restrict__ Q, __half* __restrict__ K, __half* __restrict__ V)
{
    int z = blockIdx.z;
    const __half* A = (z == 0) ? xq : (z == 1) ? xk : xv;
    const __half* W = (z == 0) ? wq : (z == 1) ? wk : wv;
    const float* bias = (z == 0) ? bq : (z == 1) ? bk : bv;
    __half* C = (z == 0) ? Q : (z == 1) ? K : V;
    float scale = (z == 0) ? (0.125f * 1.4426950408889634f) : 1.0f;
    gemm_body(A, W, bias, C, scale, 1);
}

__global__ __launch_bounds__(256, 2) void gemm_o(
    const __half* __restrict__ A, const __half* __restrict__ W,
    const float* __restrict__ bias, float* __restrict__ C)
{
    gemm_body(A, W, bias, C, 1.0f, 0);
}

// ---------------------------------------------------------------------------
// Flash attention, fp16 mma (R13 version). Block = (128 q-rows, head, batch),
// 4 warps, 32 q-rows per warp (two 16-row sets share every K/V fragment).
// log2-domain scores, ex2.approx.f16x2, ones-column row sums. Heavy first.
// ---------------------------------------------------------------------------
#define AST 72
#define ATTN_SMEM (4 * 64 * AST * (int)sizeof(__half))

__global__ __launch_bounds__(128) void attn_h(int dummy) {
    extern __shared__ __half asm_[];
    __half* Ks = asm_;                        // [2][64*AST]
    __half* Vs = asm_ + 2 * 64 * AST;         // [2][64*AST]

    int tid  = threadIdx.x;
    int lane = tid & 31, warp = tid >> 5;
    int g = lane >> 2, t = lane & 3;
    int q0 = ((int)gridDim.x - 1 - (int)blockIdx.x) * 128;
    int h  = blockIdx.y;
    int n  = blockIdx.z;

    int row_w = q0 + warp * 32;    // 32 rows per warp

    const __half* Qg = g_Qh + (size_t)n * L_ * D_ + (size_t)row_w * D_ + h * DK_;
    const __half* Kg = g_Kh + (size_t)n * L_ * D_ + h * DK_;
    const __half* Vg = g_Vh + (size_t)n * L_ * D_ + h * DK_;

    int brow = (lane >> 4) * 8 + (lane & 7);
    int bcol = ((lane >> 3) & 1) * 8;
    int vrow = ((lane >> 3) & 1) * 8 + (lane & 7);
    int vcol = (lane >> 4) * 8;

    // Q fragments: 2 row-sets of 16 rows each
    unsigned qa[2][4][4];
    #pragma unroll
    for (int s = 0; s < 2; s++)
        #pragma unroll
        for (int kk = 0; kk < 4; kk++) {
            qa[s][kk][0] = *(const unsigned*)&Qg[(size_t)(s * 16 + g) * D_     + kk * 16 + 2 * t];
            qa[s][kk][1] = *(const unsigned*)&Qg[(size_t)(s * 16 + g + 8) * D_ + kk * 16 + 2 * t];
            qa[s][kk][2] = *(const unsigned*)&Qg[(size_t)(s * 16 + g) * D_     + kk * 16 + 2 * t + 8];
            qa[s][kk][3] = *(const unsigned*)&Qg[(size_t)(s * 16 + g + 8) * D_ + kk * 16 + 2 * t + 8];
        }

    float oc[2][8][4];
    #pragma unroll
    for (int s = 0; s < 2; s++)
        #pragma unroll
        for (int nf = 0; nf < 8; nf++)
            #pragma unroll
            for (int i = 0; i < 4; i++) oc[s][nf][i] = 0.f;
    float ol[2][4];
    #pragma unroll
    for (int s = 0; s < 2; s++)
        #pragma unroll
        for (int i = 0; i < 4; i++) ol[s][i] = 0.f;

    float m[2][2];   // running max per set, per row-half (g / g+8)
    m[0][0] = m[0][1] = m[1][0] = m[1][1] = -1e30f;
    int rmax_w = row_w + 31;

    int len   = g_len[n];
    int jend  = min(q0 + 128, len);
    int tiles = (jend + 63) >> 6;

    // prologue: tile 0 (K, V) — 128 threads stage 64x64-half K and V
    {
        #pragma unroll
        for (int i = 0; i < 4; i++) {
            int idx = tid + i * 128;      // 0..511
            int r = idx >> 3, u = idx & 7;
            CP16(smaddr(&Ks[r * AST + u * 8]), Kg + (size_t)r * D_ + u * 8);
            CP16(smaddr(&Vs[r * AST + u * 8]), Vg + (size_t)r * D_ + u * 8);
        }
        CP_COMMIT();
    }

    #pragma unroll 1
    for (int it = 0; it < tiles; it++) {
        int cur = it & 1;
        int j0  = it * 64;
        if (it + 1 < tiles) {
            int jn = j0 + 64;
            __half* Kd = Ks + (cur ^ 1) * 64 * AST;
            __half* Vd = Vs + (cur ^ 1) * 64 * AST;
            #pragma unroll
            for (int i = 0; i < 4; i++) {
                int idx = tid + i * 128;
                int r = idx >> 3, u = idx & 7;
                CP16(smaddr(&Kd[r * AST + u * 8]), Kg + (size_t)(jn + r) * D_ + u * 8);
                CP16(smaddr(&Vd[r * AST + u * 8]), Vg + (size_t)(jn + r) * D_ + u * 8);
            }
            CP_COMMIT();
            CP_WAIT(1);
        } else {
            CP_WAIT(0);
        }
        __syncthreads();

        if (j0 <= rmax_w) {
            const __half* Kb = Ks + cur * 64 * AST;
            const __half* Vb = Vs + cur * 64 * AST;

            // S = Q K^T (log2 domain), both row-sets share K fragments
            float sc[2][8][4];
            #pragma unroll
            for (int s = 0; s < 2; s++)
                #pragma unroll
                for (int nf = 0; nf < 8; nf++)
                    #pragma unroll
                    for (int i = 0; i < 4; i++) sc[s][nf][i] = 0.f;

            #pragma unroll
            for (int kk = 0; kk < 4; kk++) {
                unsigned b[8][2];
                #pragma unroll
                for (int np = 0; np < 4; np++) {
                    unsigned addr = smaddr(&Kb[(np * 16 + brow) * AST + kk * 16 + bcol]);
                    LDM_X4(b[2 * np][0], b[2 * np][1], b[2 * np + 1][0], b[2 * np + 1][1], addr);
                }
                #pragma unroll
                for (int nf = 0; nf < 8; nf++) {
                    mma16(sc[0][nf], qa[0][kk], b[nf][0], b[nf][1]);
                    mma16(sc[1][nf], qa[1][kk], b[nf][0], b[nf][1]);
                }
            }

            // Masking only on diagonal / len-boundary tiles
            bool need_mask = (j0 + 63 > row_w) || (j0 + 64 > len);
            if (need_mask) {
                #pragma unroll
                for (int s = 0; s < 2; s++) {
                    int r0 = row_w + s * 16 + g;
                    int r1 = r0 + 8;
                    #pragma unroll
                    for (int nf = 0; nf < 8; nf++) {
                        int c0i = j0 + nf * 8 + 2 * t, c1i = c0i + 1;
                        if (c0i > r0 || c0i >= len) sc[s][nf][0] = -1e30f;
                        if (c1i > r0 || c1i >= len) sc[s][nf][1] = -1e30f;
                        if (c0i > r1 || c0i >= len) sc[s][nf][2] = -1e30f;
                        if (c1i > r1 || c1i >= len) sc[s][nf][3] = -1e30f;
                    }
                }
            }

            // Row max + rescale per set
            #pragma unroll
            for (int s = 0; s < 2; s++) {
                float rm0 = -1e30f, rm1 = -1e30f;
                #pragma unroll
                for (int nf = 0; nf < 8; nf++) {
                    rm0 = fmaxf(rm0, fmaxf(sc[s][nf][0], sc[s][nf][1]));
                    rm1 = fmaxf(rm1, fmaxf(sc[s][nf][2], sc[s][nf][3]));
                }
                rm0 = fmaxf(rm0, __shfl_xor_sync(0xffffffffu, rm0, 1));
                rm0 = fmaxf(rm0, __shfl_xor_sync(0xffffffffu, rm0, 2));
                rm1 = fmaxf(rm1, __shfl_xor_sync(0xffffffffu, rm1, 1));
                rm1 = fmaxf(rm1, __shfl_xor_sync(0xffffffffu, rm1, 2));

                float mn0 = fmaxf(m[s][0], rm0), mn1 = fmaxf(m[s][1], rm1);
                float al0 = exp2f(m[s][0] - mn0), al1 = exp2f(m[s][1] - mn1);
                m[s][0] = mn0; m[s][1] = mn1;

                #pragma unroll
                for (int nf = 0; nf < 8; nf++) {
                    oc[s][nf][0] *= al0; oc[s][nf][1] *= al0;
                    oc[s][nf][2] *= al1; oc[s][nf][3] *= al1;
                }
                ol[s][0] *= al0; ol[s][1] *= al0;
                ol[s][2] *= al1; ol[s][3] *= al1;
            }

            // P = exp2(S - m) fp16; V fragments shared by both sets
            #pragma unroll
            for (int kk = 0; kk < 4; kk++) {
                unsigned pa[2][4];
                #pragma unroll
                for (int s = 0; s < 2; s++) {
                    pa[s][0] = ex2h2(h2bits(sc[s][2 * kk][0] - m[s][0],     sc[s][2 * kk][1] - m[s][0]));
                    pa[s][1] = ex2h2(h2bits(sc[s][2 * kk][2] - m[s][1],     sc[s][2 * kk][3] - m[s][1]));
                    pa[s][2] = ex2h2(h2bits(sc[s][2 * kk + 1][0] - m[s][0], sc[s][2 * kk + 1][1] - m[s][0]));
                    pa[s][3] = ex2h2(h2bits(sc[s][2 * kk + 1][2] - m[s][1], sc[s][2 * kk + 1][3] - m[s][1]));
                }
                #pragma unroll
                for (int np = 0; np < 4; np++) {
                    unsigned v0, v1, v2, v3;
                    unsigned addr = smaddr(&Vb[(kk * 16 + vrow) * AST + np * 16 + vcol]);
                    LDM_X4T(v0, v1, v2, v3, addr);
                    mma16(oc[0][2 * np],     pa[0], v0, v1);
                    mma16(oc[0][2 * np + 1], pa[0], v2, v3);
                    mma16(oc[1][2 * np],     pa[1], v0, v1);
                    mma16(oc[1][2 * np + 1], pa[1], v2, v3);
                }
                mma16(ol[0], pa[0], HONES, HONES);
                mma16(ol[1], pa[1], HONES, HONES);
            }
        }
        __syncthreads();
    }

    // Epilogue: normalize by MMA-accumulated row sums, write O (half)
    #pragma unroll
    for (int s = 0; s < 2; s++) {
        float inv0 = 1.0f / ol[s][0], inv1 = 1.0f / ol[s][2];
        __half* Og = g_Oh + ((size_t)(n * L_ + row_w + s * 16)) * D_ + h * DK_;
        #pragma unroll
        for (int nf = 0; nf < 8; nf++) {
            int cb = nf * 8 + 2 * t;
            *(unsigned*)(Og + (size_t)g * D_ + cb) =
                h2bits(oc[s][nf][0] * inv0, oc[s][nf][1] * inv0);
            *(unsigned*)(Og + (size_t)(g + 8) * D_ + cb) =
                h2bits(oc[s][nf][2] * inv1, oc[s][nf][3] * inv1);
        }
    }
}

// ---------------------------------------------------------------------------
extern "C" void kernel_launch(void* const* d_in, const int* in_sizes, int n_in,
                              void* d_out, int out_size)
{
    const float* x_q = (const float*)d_in[0];
    const float* x_k = (const float*)d_in[1];
    const float* x_v = (const float*)d_in[2];
    const int*   pm  = (const int*)  d_in[3];
    // d_in[4] = attention_mask (causal) — handled analytically
    const float* Wq = (const float*)d_in[5];
    const float* bq = (const float*)d_in[6];
    const float* Wk = (const float*)d_in[7];
    const float* bk = (const float*)d_in[8];
    const float* Wv = (const float*)d_in[9];
    const float* bv = (const float*)d_in[10];
    const float* Wo = (const float*)d_in[11];
    const float* bo = (const float*)d_in[12];
    float* out = (float*)d_out;

    __half *xqh, *xkh, *xvh, *wqh, *wkh, *wvh, *woh, *Qh, *Kh, *Vh, *Oh;
    cudaGetSymbolAddress((void**)&xqh, g_xqh);
    cudaGetSymbolAddress((void**)&xkh, g_xkh);
    cudaGetSymbolAddress((void**)&xvh, g_xvh);
    cudaGetSymbolAddress((void**)&wqh, g_wqh);
    cudaGetSymbolAddress((void**)&wkh, g_wkh);
    cudaGetSymbolAddress((void**)&wvh, g_wvh);
    cudaGetSymbolAddress((void**)&woh, g_woh);
    cudaGetSymbolAddress((void**)&Qh,  g_Qh);
    cudaGetSymbolAddress((void**)&Kh,  g_Kh);
    cudaGetSymbolAddress((void**)&Vh,  g_Vh);
    cudaGetSymbolAddress((void**)&Oh,  g_Oh);

    cudaFuncSetAttribute(gemm_qkv, cudaFuncAttributeMaxDynamicSharedMemorySize,
                         GEMM_SMEM);
    cudaFuncSetAttribute(gemm_o, cudaFuncAttributeMaxDynamicSharedMemorySize,
                         GEMM_SMEM);
    cudaFuncSetAttribute(attn_h, cudaFuncAttributeMaxDynamicSharedMemorySize,
                         ATTN_SMEM);

    // One prep launch: x/W conversions + len reduction
    prep_kernel<<<dim3(X4_ / 512, 8), 256>>>(
        (const float4*)x_q, (const float4*)x_k, (const float4*)x_v,
        (const float4*)Wq, (const float4*)Wk, (const float4*)Wv,
        (const float4*)Wo, pm);

    gemm_qkv<<<dim3(M_ / 128, D_ / 128, 3), 256, GEMM_SMEM>>>(
        xqh, xkh, xvh, wqh, wkh, wvh, bq, bk, bv, Qh, Kh, Vh);

    attn_h<<<dim3(L_ / 128, H_, N_), 128, ATTN_SMEM>>>(0);

    gemm_o<<<dim3(M_ / 128, D_ / 128), 256, GEMM_SMEM>>>(Oh, woh, bo, out);
}

// round 16
// speedup vs baseline: 1.1034x; 1.0096x over previous
#include <cuda_runtime.h>
#include <cuda_fp16.h>
#include <math.h>

#define N_  4
#define L_  2048
#define D_  512
#define H_  8
#define DK_ 64
#define M_  (N_ * L_)

// Scratch (device globals: no allocation allowed in kernel_launch)
__device__ __half g_xqh[(size_t)M_ * D_];
__device__ __half g_xkh[(size_t)M_ * D_];
__device__ __half g_xvh[(size_t)M_ * D_];
__device__ __half g_wqh[(size_t)D_ * D_];
__device__ __half g_wkh[(size_t)D_ * D_];
__device__ __half g_wvh[(size_t)D_ * D_];
__device__ __half g_woh[(size_t)D_ * D_];
__device__ __half g_Qh[(size_t)M_ * D_];
__device__ __half g_Kh[(size_t)M_ * D_];
__device__ __half g_Vh[(size_t)M_ * D_];
__device__ __half g_Oh[(size_t)M_ * D_];
__device__ int    g_len[N_];

#define HONES 0x3C003C00u   // half2(1.0, 1.0)

// ---------------------------------------------------------------------------
__device__ __forceinline__ void mma16(float c[4], const unsigned a[4],
                                      unsigned b0, unsigned b1) {
    asm volatile(
        "mma.sync.aligned.m16n8k16.row.col.f32.f16.f16.f32 "
        "{%0,%1,%2,%3}, {%4,%5,%6,%7}, {%8,%9}, {%0,%1,%2,%3};\n"
        : "+f"(c[0]), "+f"(c[1]), "+f"(c[2]), "+f"(c[3])
        : "r"(a[0]), "r"(a[1]), "r"(a[2]), "r"(a[3]), "r"(b0), "r"(b1));
}

__device__ __forceinline__ unsigned smaddr(const void* p) {
    return (unsigned)__cvta_generic_to_shared(p);
}
#define LDM_X4(r0, r1, r2, r3, addr) \
    asm volatile("ldmatrix.sync.aligned.m8n8.x4.shared.b16 {%0,%1,%2,%3}, [%4];" \
        : "=r"(r0), "=r"(r1), "=r"(r2), "=r"(r3) : "r"(addr))
#define LDM_X4T(r0, r1, r2, r3, addr) \
    asm volatile("ldmatrix.sync.aligned.m8n8.x4.trans.shared.b16 {%0,%1,%2,%3}, [%4];" \
        : "=r"(r0), "=r"(r1), "=r"(r2), "=r"(r3) : "r"(addr))
#define CP16(sm, gm) asm volatile("cp.async.cg.shared.global [%0], [%1], 16;\n" :: "r"(sm), "l"(gm))
#define CP_COMMIT()  asm volatile("cp.async.commit_group;\n")
#define CP_WAIT(n)   asm volatile("cp.async.wait_group %0;\n" :: "n"(n))

__device__ __forceinline__ unsigned h2bits(float lo, float hi) {
    __half2 h = __floats2half2_rn(lo, hi);
    return *(unsigned*)&h;
}

// packed half2 2^x
__device__ __forceinline__ unsigned ex2h2(unsigned x) {
    unsigned r;
    asm volatile("ex2.approx.f16x2 %0, %1;" : "=r"(r) : "r"(x));
    return r;
}

// packed f32x2 helpers (Blackwell FFMA2 path; movs dissolve into reg pairs)
__device__ __forceinline__ unsigned long long pack2(float a, float b) {
    unsigned long long p;
    asm("mov.b64 %0, {%1, %2};" : "=l"(p) : "f"(a), "f"(b));
    return p;
}
__device__ __forceinline__ void mul2(float& a, float& b, unsigned long long s2) {
    unsigned long long p = pack2(a, b);
    asm("mul.rn.f32x2 %0, %0, %1;" : "+l"(p) : "l"(s2));
    asm("mov.b64 {%0, %1}, %2;" : "=f"(a), "=f"(b) : "l"(p));
}
// exp2(s0+off, s1+off) packed -> half2 bits
__device__ __forceinline__ unsigned expsub(float s0, float s1,
                                           unsigned long long negmn2) {
    unsigned long long p = pack2(s0, s1);
    asm("add.rn.f32x2 %0, %0, %1;" : "+l"(p) : "l"(negmn2));
    float a, b;
    asm("mov.b64 {%0, %1}, %2;" : "=f"(a), "=f"(b) : "l"(p));
    return ex2h2(h2bits(a, b));
}

// ---------------------------------------------------------------------------
// prep: one launch does all float->half conversions AND the len reduction.
// blockIdx.y: 0..2 -> x_q/x_k/x_v, 3..6 -> weights, 7 -> len.
// ---------------------------------------------------------------------------
#define X4_ (M_ * D_ / 4)
#define W4_ (D_ * D_ / 4)

__global__ void prep_kernel(const float4* __restrict__ xq,
                            const float4* __restrict__ xk,
                            const float4* __restrict__ xv,
                            const float4* __restrict__ Wq,
                            const float4* __restrict__ Wk,
                            const float4* __restrict__ Wv,
                            const float4* __restrict__ Wo,
                            const int* __restrict__ pm) {
    int y = blockIdx.y;
    if (y < 3) {
        const float4* s = (y == 0) ? xq : (y == 1) ? xk : xv;
        uint2* d = (y == 0) ? (uint2*)g_xqh : (y == 1) ? (uint2*)g_xkh : (uint2*)g_xvh;
        int i = blockIdx.x * 512 + threadIdx.x;
        float4 v0 = s[i], v1 = s[i + 256];
        d[i]       = make_uint2(h2bits(v0.x, v0.y), h2bits(v0.z, v0.w));
        d[i + 256] = make_uint2(h2bits(v1.x, v1.y), h2bits(v1.z, v1.w));
    } else if (y < 7) {
        if (blockIdx.x >= W4_ / 512) return;
        const float4* s = (y == 3) ? Wq : (y == 4) ? Wk : (y == 5) ? Wv : Wo;
        uint2* d = (y == 3) ? (uint2*)g_wqh : (y == 4) ? (uint2*)g_wkh
                 : (y == 5) ? (uint2*)g_wvh : (uint2*)g_woh;
        int i = blockIdx.x * 512 + threadIdx.x;
        float4 v0 = s[i], v1 = s[i + 256];
        d[i]       = make_uint2(h2bits(v0.x, v0.y), h2bits(v0.z, v0.w));
        d[i + 256] = make_uint2(h2bits(v1.x, v1.y), h2bits(v1.z, v1.w));
    } else {
        if (blockIdx.x >= N_) return;
        __shared__ int red[8];
        int n = blockIdx.x;
        int best = 0;
        for (int j = threadIdx.x; j < L_; j += 256)
            if (pm[(size_t)n * L_ + j] != 0) best = max(best, j + 1);
        #pragma unroll
        for (int off = 16; off; off >>= 1)
            best = max(best, __shfl_xor_sync(0xffffffffu, best, off));
        if ((threadIdx.x & 31) == 0) red[threadIdx.x >> 5] = best;
        __syncthreads();
        if (threadIdx.x == 0) {
            int b = red[0];
            #pragma unroll
            for (int w = 1; w < 8; w++) b = max(b, red[w]);
            g_len[n] = b;
        }
    }
}

// ---------------------------------------------------------------------------
// GEMM body (R10): 128x128 tile, 256 threads, 8 warps (64x32 warp tile),
// fp16 mma, cp.async 3-stage pipelined chunks (K=64).
// ---------------------------------------------------------------------------
#define GST 72
#define GNB (128 * GST)
#define GEMM_SMEM (3 * 2 * GNB * (int)sizeof(__half))

__device__ __forceinline__ void gemm_stage(__half* As, __half* Ws,
                                           const __half* __restrict__ A,
                                           const __half* __restrict__ W,
                                           int row0, int col0, int k0, int tid) {
    #pragma unroll
    for (int i = 0; i < 4; i++) {
        int idx = tid + i * 256;
        int r = idx >> 3, u = idx & 7;
        CP16(smaddr(&As[r * GST + u * 8]), A + (size_t)(row0 + r) * D_ + k0 + u * 8);
        CP16(smaddr(&Ws[r * GST + u * 8]), W + (size_t)(col0 + r) * D_ + k0 + u * 8);
    }
}

__device__ __forceinline__ void gemm_body(
    const __half* __restrict__ A, const __half* __restrict__ W,
    const float* __restrict__ bias, void* __restrict__ Cout, float scale,
    int half_out)
{
    extern __shared__ __half gsm[];
    __half* As = gsm;            // [3][GNB]
    __half* Ws = gsm + 3 * GNB;  // [3][GNB]

    int tid  = threadIdx.x;
    int lane = tid & 31, warp = tid >> 5;
    int g = lane >> 2, t = lane & 3;
    int wm = warp & 1, wn = warp >> 1;
    int row0 = blockIdx.x * 128;
    int col0 = blockIdx.y * 128;

    int arow = ((lane >> 3) & 1) * 8 + (lane & 7);
    int acol = (lane >> 4) * 8;
    int brow = (lane >> 4) * 8 + (lane & 7);
    int bcol = ((lane >> 3) & 1) * 8;

    float c[4][4][4];
    #pragma unroll
    for (int mf = 0; mf < 4; mf++)
        #pragma unroll
        for (int nf = 0; nf < 4; nf++)
            #pragma unroll
            for (int i = 0; i < 4; i++) c[mf][nf][i] = 0.f;

    gemm_stage(As,       Ws,       A, W, row0, col0, 0,  tid); CP_COMMIT();
    gemm_stage(As + GNB, Ws + GNB, A, W, row0, col0, 64, tid); CP_COMMIT();

    #pragma unroll 1
    for (int ch = 0; ch < 8; ch++) {
        int bi = ch % 3;
        if (ch < 7) { CP_WAIT(1); } else { CP_WAIT(0); }
        __syncthreads();
        if (ch + 2 < 8) {
            int nb = (ch + 2) % 3;
            gemm_stage(As + nb * GNB, Ws + nb * GNB, A, W, row0, col0,
                       (ch + 2) * 64, tid);
            CP_COMMIT();
        }

        const __half* Ab = As + bi * GNB;
        const __half* Wb = Ws + bi * GNB;

        #pragma unroll
        for (int kk = 0; kk < 4; kk++) {
            unsigned a[4][4], b[4][2];
            #pragma unroll
            for (int mf = 0; mf < 4; mf++) {
                unsigned addr = smaddr(&Ab[(wm * 64 + mf * 16 + arow) * GST + kk * 16 + acol]);
                LDM_X4(a[mf][0], a[mf][1], a[mf][2], a[mf][3], addr);
            }
            #pragma unroll
            for (int np = 0; np < 2; np++) {
                unsigned addr = smaddr(&Wb[(wn * 32 + np * 16 + brow) * GST + kk * 16 + bcol]);
                LDM_X4(b[2 * np][0], b[2 * np][1], b[2 * np + 1][0], b[2 * np + 1][1], addr);
            }
            #pragma unroll
            for (int mf = 0; mf < 4; mf++)
                #pragma unroll
                for (int nf = 0; nf < 4; nf++)
                    mma16(c[mf][nf], a[mf], b[nf][0], b[nf][1]);
        }
    }

    // Epilogue
    #pragma unroll
    for (int mf = 0; mf < 4; mf++) {
        int r0 = row0 + wm * 64 + mf * 16 + g;
        #pragma unroll
        for (int nf = 0; nf < 4; nf++) {
            int cc = col0 + wn * 32 + nf * 8 + 2 * t;
            float b0 = bias[cc], b1 = bias[cc + 1];
            float v00 = (c[mf][nf][0] + b0) * scale;
            float v01 = (c[mf][nf][1] + b1) * scale;
            float v10 = (c[mf][nf][2] + b0) * scale;
            float v11 = (c[mf][nf][3] + b1) * scale;
            if (half_out) {
                __half* C = (__half*)Cout;
                *(unsigned*)(C + (size_t)r0 * D_ + cc)       = h2bits(v00, v01);
                *(unsigned*)(C + (size_t)(r0 + 8) * D_ + cc) = h2bits(v10, v11);
            } else {
                float* C = (float*)Cout;
                *(float2*)(C + (size_t)r0 * D_ + cc)       = make_float2(v00, v01);
                *(float2*)(C + (size_t)(r0 + 8) * D_ + cc) = make_float2(v10, v11);
            }
        }
    }
}

// Fused Q/K/V projection. Q scale folds 1/sqrt(dk) and log2(e) -> exp2 domain.
__global__ __launch_bounds__(256, 2) void gemm_qkv(
    const __half* __restrict__ xq, const __half* __restrict__ xk,
    const __half* __restrict__ xv,
    const __half* __restrict__ wq, const __half* __restrict__ wk,
    const __half* __restrict__ wv,
    const float* __restrict__ bq, const float* __restrict__ bk,
    const float* __restrict__ bv,
    __half* __restrict__ Q, __half* __restrict__ K, __half* __restrict__ V)
{
    int z = blockIdx.z;
    const __half* A = (z == 0) ? xq : (z == 1) ? xk : xv;
    const __half* W = (z == 0) ? wq : (z == 1) ? wk : wv;
    const float* bias = (z == 0) ? bq : (z == 1) ? bk : bv;
    __half* C = (z == 0) ? Q : (z == 1) ? K : V;
    float scale = (z == 0) ? (0.125f * 1.4426950408889634f) : 1.0f;
    gemm_body(A, W, bias, C, scale, 1);
}

__global__ __launch_bounds__(256, 2) void gemm_o(
    const __half* __restrict__ A, const __half* __restrict__ W,
    const float* __restrict__ bias, float* __restrict__ C)
{
    gemm_body(A, W, bias, C, 1.0f, 0);
}

// ---------------------------------------------------------------------------
// Flash attention, fp16 mma. Block = (128 q-rows, head, batch), 4 warps,
// 32 q-rows per warp (two 16-row sets share every K/V fragment).
// log2-domain scores, ex2.approx.f16x2, ones-column row sums, packed f32x2
// rescale/exp-input math. Heavy (high-q0) blocks first.
// ---------------------------------------------------------------------------
#define AST 72
#define ATTN_SMEM (4 * 64 * AST * (int)sizeof(__half))

__global__ __launch_bounds__(128) void attn_h(int dummy) {
    extern __shared__ __half asm_[];
    __half* Ks = asm_;                        // [2][64*AST]
    __half* Vs = asm_ + 2 * 64 * AST;         // [2][64*AST]

    int tid  = threadIdx.x;
    int lane = tid & 31, warp = tid >> 5;
    int g = lane >> 2, t = lane & 3;
    int q0 = ((int)gridDim.x - 1 - (int)blockIdx.x) * 128;
    int h  = blockIdx.y;
    int n  = blockIdx.z;

    int row_w = q0 + warp * 32;    // 32 rows per warp

    const __half* Qg = g_Qh + (size_t)n * L_ * D_ + (size_t)row_w * D_ + h * DK_;
    const __half* Kg = g_Kh + (size_t)n * L_ * D_ + h * DK_;
    const __half* Vg = g_Vh + (size_t)n * L_ * D_ + h * DK_;

    int brow = (lane >> 4) * 8 + (lane & 7);
    int bcol = ((lane >> 3) & 1) * 8;
    int vrow = ((lane >> 3) & 1) * 8 + (lane & 7);
    int vcol = (lane >> 4) * 8;

    // Q fragments: 2 row-sets of 16 rows each
    unsigned qa[2][4][4];
    #pragma unroll
    for (int s = 0; s < 2; s++)
        #pragma unroll
        for (int kk = 0; kk < 4; kk++) {
            qa[s][kk][0] = *(const unsigned*)&Qg[(size_t)(s * 16 + g) * D_     + kk * 16 + 2 * t];
            qa[s][kk][1] = *(const unsigned*)&Qg[(size_t)(s * 16 + g + 8) * D_ + kk * 16 + 2 * t];
            qa[s][kk][2] = *(const unsigned*)&Qg[(size_t)(s * 16 + g) * D_     + kk * 16 + 2 * t + 8];
            qa[s][kk][3] = *(const unsigned*)&Qg[(size_t)(s * 16 + g + 8) * D_ + kk * 16 + 2 * t + 8];
        }

    float oc[2][8][4];
    #pragma unroll
    for (int s = 0; s < 2; s++)
        #pragma unroll
        for (int nf = 0; nf < 8; nf++)
            #pragma unroll
            for (int i = 0; i < 4; i++) oc[s][nf][i] = 0.f;
    float ol[2][4];
    #pragma unroll
    for (int s = 0; s < 2; s++)
        #pragma unroll
        for (int i = 0; i < 4; i++) ol[s][i] = 0.f;

    float m[2][2];   // running max per set, per row-half (g / g+8)
    m[0][0] = m[0][1] = m[1][0] = m[1][1] = -1e30f;
    int rmax_w = row_w + 31;

    int len   = g_len[n];
    int jend  = min(q0 + 128, len);
    int tiles = (jend + 63) >> 6;

    // prologue: tile 0 (K, V) — 128 threads stage 64x64-half K and V
    {
        #pragma unroll
        for (int i = 0; i < 4; i++) {
            int idx = tid + i * 128;      // 0..511
            int r = idx >> 3, u = idx & 7;
            CP16(smaddr(&Ks[r * AST + u * 8]), Kg + (size_t)r * D_ + u * 8);
            CP16(smaddr(&Vs[r * AST + u * 8]), Vg + (size_t)r * D_ + u * 8);
        }
        CP_COMMIT();
    }

    #pragma unroll 1
    for (int it = 0; it < tiles; it++) {
        int cur = it & 1;
        int j0  = it * 64;
        if (it + 1 < tiles) {
            int jn = j0 + 64;
            __half* Kd = Ks + (cur ^ 1) * 64 * AST;
            __half* Vd = Vs + (cur ^ 1) * 64 * AST;
            #pragma unroll
            for (int i = 0; i < 4; i++) {
                int idx = tid + i * 128;
                int r = idx >> 3, u = idx & 7;
                CP16(smaddr(&Kd[r * AST + u * 8]), Kg + (size_t)(jn + r) * D_ + u * 8);
                CP16(smaddr(&Vd[r * AST + u * 8]), Vg + (size_t)(jn + r) * D_ + u * 8);
            }
            CP_COMMIT();
            CP_WAIT(1);
        } else {
            CP_WAIT(0);
        }
        __syncthreads();

        if (j0 <= rmax_w) {
            const __half* Kb = Ks + cur * 64 * AST;
            const __half* Vb = Vs + cur * 64 * AST;

            // S = Q K^T (log2 domain), both row-sets share K fragments
            float sc[2][8][4];
            #pragma unroll
            for (int s = 0; s < 2; s++)
                #pragma unroll
                for (int nf = 0; nf < 8; nf++)
                    #pragma unroll
                    for (int i = 0; i < 4; i++) sc[s][nf][i] = 0.f;

            #pragma unroll
            for (int kk = 0; kk < 4; kk++) {
                unsigned b[8][2];
                #pragma unroll
                for (int np = 0; np < 4; np++) {
                    unsigned addr = smaddr(&Kb[(np * 16 + brow) * AST + kk * 16 + bcol]);
                    LDM_X4(b[2 * np][0], b[2 * np][1], b[2 * np + 1][0], b[2 * np + 1][1], addr);
                }
                #pragma unroll
                for (int nf = 0; nf < 8; nf++) {
                    mma16(sc[0][nf], qa[0][kk], b[nf][0], b[nf][1]);
                    mma16(sc[1][nf], qa[1][kk], b[nf][0], b[nf][1]);
                }
            }

            // Masking only on diagonal / len-boundary tiles
            bool need_mask = (j0 + 63 > row_w) || (j0 + 64 > len);
            if (need_mask) {
                #pragma unroll
                for (int s = 0; s < 2; s++) {
                    int r0 = row_w + s * 16 + g;
                    int r1 = r0 + 8;
                    #pragma unroll
                    for (int nf = 0; nf < 8; nf++) {
                        int c0i = j0 + nf * 8 + 2 * t, c1i = c0i + 1;
                        if (c0i > r0 || c0i >= len) sc[s][nf][0] = -1e30f;
                        if (c1i > r0 || c1i >= len) sc[s][nf][1] = -1e30f;
                        if (c0i > r1 || c0i >= len) sc[s][nf][2] = -1e30f;
                        if (c1i > r1 || c1i >= len) sc[s][nf][3] = -1e30f;
                    }
                }
            }

            // Row max + packed rescale per set
            unsigned long long negmn[2][2];
            #pragma unroll
            for (int s = 0; s < 2; s++) {
                float rm0 = -1e30f, rm1 = -1e30f;
                #pragma unroll
                for (int nf = 0; nf < 8; nf++) {
                    rm0 = fmaxf(rm0, fmaxf(sc[s][nf][0], sc[s][nf][1]));
                    rm1 = fmaxf(rm1, fmaxf(sc[s][nf][2], sc[s][nf][3]));
                }
                rm0 = fmaxf(rm0, __shfl_xor_sync(0xffffffffu, rm0, 1));
                rm0 = fmaxf(rm0, __shfl_xor_sync(0xffffffffu, rm0, 2));
                rm1 = fmaxf(rm1, __shfl_xor_sync(0xffffffffu, rm1, 1));
                rm1 = fmaxf(rm1, __shfl_xor_sync(0xffffffffu, rm1, 2));

                float mn0 = fmaxf(m[s][0], rm0), mn1 = fmaxf(m[s][1], rm1);
                float al0 = exp2f(m[s][0] - mn0), al1 = exp2f(m[s][1] - mn1);
                m[s][0] = mn0; m[s][1] = mn1;
                negmn[s][0] = pack2(-mn0, -mn0);
                negmn[s][1] = pack2(-mn1, -mn1);

                unsigned long long al00 = pack2(al0, al0);
                unsigned long long al11 = pack2(al1, al1);
                #pragma unroll
                for (int nf = 0; nf < 8; nf++) {
                    mul2(oc[s][nf][0], oc[s][nf][1], al00);
                    mul2(oc[s][nf][2], oc[s][nf][3], al11);
                }
                mul2(ol[s][0], ol[s][1], al00);
                mul2(ol[s][2], ol[s][3], al11);
            }

            // P = exp2(S - m) fp16 (packed sub + packed exp); V frags shared
            #pragma unroll
            for (int kk = 0; kk < 4; kk++) {
                unsigned pa[2][4];
                #pragma unroll
                for (int s = 0; s < 2; s++) {
                    pa[s][0] = expsub(sc[s][2 * kk][0],     sc[s][2 * kk][1],     negmn[s][0]);
                    pa[s][1] = expsub(sc[s][2 * kk][2],     sc[s][2 * kk][3],     negmn[s][1]);
                    pa[s][2] = expsub(sc[s][2 * kk + 1][0], sc[s][2 * kk + 1][1], negmn[s][0]);
                    pa[s][3] = expsub(sc[s][2 * kk + 1][2], sc[s][2 * kk + 1][3], negmn[s][1]);
                }
                #pragma unroll
                for (int np = 0; np < 4; np++) {
                    unsigned v0, v1, v2, v3;
                    unsigned addr = smaddr(&Vb[(kk * 16 + vrow) * AST + np * 16 + vcol]);
                    LDM_X4T(v0, v1, v2, v3, addr);
                    mma16(oc[0][2 * np],     pa[0], v0, v1);
                    mma16(oc[0][2 * np + 1], pa[0], v2, v3);
                    mma16(oc[1][2 * np],     pa[1], v0, v1);
                    mma16(oc[1][2 * np + 1], pa[1], v2, v3);
                }
                mma16(ol[0], pa[0], HONES, HONES);
                mma16(ol[1], pa[1], HONES, HONES);
            }
        }
        __syncthreads();
    }

    // Epilogue: normalize by MMA-accumulated row sums, write O (half)
    #pragma unroll
    for (int s = 0; s < 2; s++) {
        float inv0 = 1.0f / ol[s][0], inv1 = 1.0f / ol[s][2];
        __half* Og = g_Oh + ((size_t)(n * L_ + row_w + s * 16)) * D_ + h * DK_;
        #pragma unroll
        for (int nf = 0; nf < 8; nf++) {
            int cb = nf * 8 + 2 * t;
            *(unsigned*)(Og + (size_t)g * D_ + cb) =
                h2bits(oc[s][nf][0] * inv0, oc[s][nf][1] * inv0);
            *(unsigned*)(Og + (size_t)(g + 8) * D_ + cb) =
                h2bits(oc[s][nf][2] * inv1, oc[s][nf][3] * inv1);
        }
    }
}

// ---------------------------------------------------------------------------
extern "C" void kernel_launch(void* const* d_in, const int* in_sizes, int n_in,
                              void* d_out, int out_size)
{
    const float* x_q = (const float*)d_in[0];
    const float* x_k = (const float*)d_in[1];
    const float* x_v = (const float*)d_in[2];
    const int*   pm  = (const int*)  d_in[3];
    // d_in[4] = attention_mask (causal) — handled analytically
    const float* Wq = (const float*)d_in[5];
    const float* bq = (const float*)d_in[6];
    const float* Wk = (const float*)d_in[7];
    const float* bk = (const float*)d_in[8];
    const float* Wv = (const float*)d_in[9];
    const float* bv = (const float*)d_in[10];
    const float* Wo = (const float*)d_in[11];
    const float* bo = (const float*)d_in[12];
    float* out = (float*)d_out;

    __half *xqh, *xkh, *xvh, *wqh, *wkh, *wvh, *woh, *Qh, *Kh, *Vh, *Oh;
    cudaGetSymbolAddress((void**)&xqh, g_xqh);
    cudaGetSymbolAddress((void**)&xkh, g_xkh);
    cudaGetSymbolAddress((void**)&xvh, g_xvh);
    cudaGetSymbolAddress((void**)&wqh, g_wqh);
    cudaGetSymbolAddress((void**)&wkh, g_wkh);
    cudaGetSymbolAddress((void**)&wvh, g_wvh);
    cudaGetSymbolAddress((void**)&woh, g_woh);
    cudaGetSymbolAddress((void**)&Qh,  g_Qh);
    cudaGetSymbolAddress((void**)&Kh,  g_Kh);
    cudaGetSymbolAddress((void**)&Vh,  g_Vh);
    cudaGetSymbolAddress((void**)&Oh,  g_Oh);

    cudaFuncSetAttribute(gemm_qkv, cudaFuncAttributeMaxDynamicSharedMemorySize,
                         GEMM_SMEM);
    cudaFuncSetAttribute(gemm_o, cudaFuncAttributeMaxDynamicSharedMemorySize,
                         GEMM_SMEM);
    cudaFuncSetAttribute(attn_h, cudaFuncAttributeMaxDynamicSharedMemorySize,
                         ATTN_SMEM);

    // One prep launch: x/W conversions + len reduction
    prep_kernel<<<dim3(X4_ / 512, 8), 256>>>(
        (const float4*)x_q, (const float4*)x_k, (const float4*)x_v,
        (const float4*)Wq, (const float4*)Wk, (const float4*)Wv,
        (const float4*)Wo, pm);

    gemm_qkv<<<dim3(M_ / 128, D_ / 128, 3), 256, GEMM_SMEM>>>(
        xqh, xkh, xvh, wqh, wkh, wvh, bq, bk, bv, Qh, Kh, Vh);

    attn_h<<<dim3(L_ / 128, H_, N_), 128, ATTN_SMEM>>>(0);

    gemm_o<<<dim3(M_ / 128, D_ / 128), 256, GEMM_SMEM>>>(Oh, woh, bo, out);
}